// round 8
// baseline (speedup 1.0000x reference)
#include <cuda_runtime.h>

#define T_LEN 512
#define B_SZ  512
#define I_SZ  100
#define H_SZ  96
#define G3    288   // 3*H
#define BCH   7     // batch rows per scan block (74 chunks x 2 dirs = 148 blocks)
#define NCHUNK 74
#define NTHR  576   // 144 row-pairs x 4 k-quarters

typedef unsigned long long u64;

// Scratch: input projections for both directions: [2][T][B][3H] fp32
static __device__ float g_xproj[2ull * T_LEN * B_SZ * G3];

// ---- packed fp32x2 helpers (sm_103a FFMA2 path; bit-identical to 2x fmaf) ----
__device__ __forceinline__ u64 ffma2(u64 a, u64 b, u64 c) {
    u64 d;
    asm("fma.rn.f32x2 %0, %1, %2, %3;" : "=l"(d) : "l"(a), "l"(b), "l"(c));
    return d;
}
__device__ __forceinline__ u64 pack2(float lo, float hi) {
    u64 p;
    asm("mov.b64 %0, {%1, %2};" : "=l"(p) : "f"(lo), "f"(hi));
    return p;
}
__device__ __forceinline__ float hsum2(u64 p) {
    float lo, hi;
    asm("mov.b64 {%0, %1}, %2;" : "=f"(lo), "=f"(hi) : "l"(p));
    return lo + hi;
}
// combine the 4 k-quarter partials held by lanes l, l^8, l^16, l^24
__device__ __forceinline__ float qreduce(float v) {
    v += __shfl_xor_sync(0xffffffffu, v, 8);
    v += __shfl_xor_sync(0xffffffffu, v, 16);
    return v;
}

__device__ __forceinline__ float fast_sigmoid(float x) {
    float e, r;
    asm("ex2.approx.f32 %0, %1;" : "=f"(e) : "f"(-1.4426950408889634f * x));
    asm("rcp.approx.f32 %0, %1;" : "=f"(r) : "f"(1.0f + e));
    return r;
}
__device__ __forceinline__ float fast_tanh(float x) {
    float e, r;
    asm("ex2.approx.f32 %0, %1;" : "=f"(e) : "f"(-2.8853900817779268f * x));
    asm("rcp.approx.f32 %0, %1;" : "=f"(r) : "f"(1.0f + e));
    return 2.0f * r - 1.0f;
}

// ---------------------------------------------------------------------------
// Projection: g_xproj[dir][row][g] = b_ih[g] + sum_k x[row][k] * w_ih[g][k]
// 576 threads. Thread handles gate-rows g0=s, g1=s+144 (s = warp*8 + lane&7)
// for k-quarter q = lane>>3. k split: {28,24,24,24} floats at offsets
// {0,28,52,76} (all 16B-aligned); quarters 1-3 zero-pad to 28.
// ---------------------------------------------------------------------------
__global__ __launch_bounds__(NTHR, 1) void proj_kernel(
    const float* __restrict__ x,
    const float* __restrict__ w_ih_f, const float* __restrict__ b_ih_f,
    const float* __restrict__ w_ih_b, const float* __restrict__ b_ih_b)
{
    const int dir    = blockIdx.x & 1;
    const int chunk  = blockIdx.x >> 1;
    const int nchunk = gridDim.x >> 1;
    const long R = (long)T_LEN * B_SZ;
    const long rows_per = (R + nchunk - 1) / nchunk;
    const long r0 = (long)chunk * rows_per;
    const long r1 = (r0 + rows_per < R) ? (r0 + rows_per) : R;

    const float* w    = dir ? w_ih_b : w_ih_f;
    const float* bias = dir ? b_ih_b : b_ih_f;
    float* xp = g_xproj + (size_t)dir * T_LEN * B_SZ * G3;

    const int t    = threadIdx.x;
    const int lane = t & 31;
    const int sl   = lane & 7;
    const int q    = lane >> 3;          // k-quarter
    const int s    = (t >> 5) * 8 + sl;  // 0..143
    const int g0   = s, g1 = s + 144;

    const int koff = (q == 0) ? 0 : (28 + 24 * (q - 1));  // {0,28,52,76} floats
    // weights: 14 u64 (28 floats) per row; quarters 1-3 pad last 2 u64 with 0
    u64 wa[14], wb[14];
    {
        const u64* p0 = (const u64*)(w + g0 * I_SZ + koff);
        const u64* p1 = (const u64*)(w + g1 * I_SZ + koff);
        #pragma unroll
        for (int j = 0; j < 12; j++) { wa[j] = p0[j]; wb[j] = p1[j]; }
        wa[12] = q ? 0ull : p0[12];  wb[12] = q ? 0ull : p1[12];
        wa[13] = q ? 0ull : p0[13];  wb[13] = q ? 0ull : p1[13];
    }
    const float bg0 = q ? 0.0f : bias[g0];
    const float bg1 = q ? 0.0f : bias[g1];

    // double-buffered stage: 16 rows x 25 float4 = 400, +8 float4 pad (overread)
    __shared__ __align__(16) float4 xs4[2][408];
    if (t < 16) xs4[t >> 3][400 + (t & 7)] = make_float4(0.f, 0.f, 0.f, 0.f);

    // prime buffer 0
    {
        int nr = (int)((r1 - r0 < 16) ? (r1 - r0) : 16);
        const float4* src = (const float4*)(x + r0 * I_SZ);
        if (t < nr * 25) xs4[0][t] = src[t];
    }
    __syncthreads();

    const int kbase = koff >> 2;  // ulonglong2 offset inside a row: {0,7,13,19}

    int buf = 0;
    for (long row0 = r0; row0 < r1; row0 += 16, buf ^= 1) {
        const int nr = (int)((r1 - row0 < 16) ? (r1 - row0) : 16);

        // prefetch next tile into a register (latency hidden by compute)
        float4 pre0;
        int pdo = 0;
        const long nrow0 = row0 + 16;
        if (nrow0 < r1) {
            const int nnr = (int)((r1 - nrow0 < 16) ? (r1 - nrow0) : 16);
            const float4* nsrc = (const float4*)(x + nrow0 * I_SZ);
            if (t < nnr * 25) { pre0 = nsrc[t]; pdo = 1; }
        }

        const ulonglong2* xb2 = (const ulonglong2*)xs4[buf];
        for (int sub = 0; sub < nr; sub += 4) {
            u64 a0[4], a1[4];
            #pragma unroll
            for (int r = 0; r < 4; r++) { a0[r] = pack2(bg0, 0.f); a1[r] = pack2(bg1, 0.f); }
            #pragma unroll
            for (int kk = 0; kk < 7; kk++) {
                #pragma unroll
                for (int r = 0; r < 4; r++) {
                    ulonglong2 hv = xb2[(sub + r) * 25 + kbase + kk];
                    a0[r] = ffma2(hv.x, wa[2 * kk],     a0[r]);
                    a0[r] = ffma2(hv.y, wa[2 * kk + 1], a0[r]);
                    a1[r] = ffma2(hv.x, wb[2 * kk],     a1[r]);
                    a1[r] = ffma2(hv.y, wb[2 * kk + 1], a1[r]);
                }
            }
            // combine k-quarters: every lane ends with the full sums
            float s0[4], s1[4];
            #pragma unroll
            for (int r = 0; r < 4; r++) {
                s0[r] = qreduce(hsum2(a0[r]));
                s1[r] = qreduce(hsum2(a1[r]));
            }
            // split the 8 stores across the 4 quarter-groups
            const int rA = 2 * (q & 1);           // 0 or 2
            const int gq = (q < 2) ? g0 : g1;
            const float vA = (q < 2) ? s0[rA]     : s1[rA];
            const float vB = (q < 2) ? s0[rA + 1] : s1[rA + 1];
            if (row0 + sub + rA     < r1) xp[(row0 + sub + rA)     * G3 + gq] = vA;
            if (row0 + sub + rA + 1 < r1) xp[(row0 + sub + rA + 1) * G3 + gq] = vB;
        }

        if (pdo) xs4[buf ^ 1][t] = pre0;
        __syncthreads();
    }
}

// ---------------------------------------------------------------------------
// Scan: block owns BCH batch rows for one direction, loops over all T.
// 576 threads: thread computes gate-rows g0=s, g1=s+144 for k-quarter
// q = lane>>3 (24 floats each, exact split). 2-level shfl combine.
// xq (x-projection) double-buffered through smem, prefetched 1 step ahead.
// ---------------------------------------------------------------------------
__global__ __launch_bounds__(NTHR, 1) void scan_kernel(
    const float* __restrict__ w_hh_f, const float* __restrict__ b_hh_f,
    const float* __restrict__ w_hh_b, const float* __restrict__ b_hh_b,
    float* __restrict__ out)
{
    const int dir = blockIdx.y;
    const int b0  = blockIdx.x * BCH;
    const float* w    = dir ? w_hh_b : w_hh_f;
    const float* bias = dir ? b_hh_b : b_hh_f;
    const float* xp = g_xproj + (size_t)dir * T_LEN * B_SZ * G3;

    const int t    = threadIdx.x;
    const int lane = t & 31;
    const int sl   = lane & 7;
    const int q    = lane >> 3;
    const int s    = (t >> 5) * 8 + sl;   // 0..143
    const int g0   = s, g1 = s + 144;

    // weights: rows g0,g1, k in [24q, 24q+24): 12 u64 each (exact, no pad)
    u64 wa[12], wb[12];
    {
        const u64* p0 = (const u64*)(w + g0 * H_SZ + 24 * q);
        const u64* p1 = (const u64*)(w + g1 * H_SZ + 24 * q);
        #pragma unroll
        for (int j = 0; j < 12; j++) { wa[j] = p0[j]; wb[j] = p1[j]; }
    }
    const float bg0 = q ? 0.0f : bias[g0];
    const float bg1 = q ? 0.0f : bias[g1];

    __shared__ __align__(16) float h_s[BCH][H_SZ];   // hidden state
    __shared__ float s_s[BCH][G3];                   // r,z: xp+hp ; n: hp
    __shared__ float xn_s[BCH][H_SZ];                // xp for n-gate
    __shared__ __align__(16) float xq_s[2][BCH * G3]; // staged x-projections

    for (int idx = t; idx < BCH * H_SZ; idx += NTHR) ((float*)h_s)[idx] = 0.0f;

    // xq loader assignment: thread t stages float4 at flat index 4t of [b][g]
    const int l_b = (4 * t) / G3;                 // batch slot (t < 504)
    const int l_g = (4 * t) % G3;
    int l_row = b0 + l_b;
    if (l_row > B_SZ - 1) l_row = B_SZ - 1;       // tail-chunk clamp

    // prime xq_s[0] with step 0
    if (t < (BCH * G3) / 4) {
        const int t0 = dir ? (T_LEN - 1) : 0;
        ((float4*)xq_s[0])[t] =
            *(const float4*)(xp + ((size_t)t0 * B_SZ + l_row) * G3 + l_g);
    }
    __syncthreads();

    int buf = 0;
    for (int it = 0; it < T_LEN; it++) {
        const int tc = dir ? (T_LEN - 1 - it) : it;

        // issue next step's xq loads now (DRAM latency hidden by this step)
        float4 pre;
        int pdo = 0;
        if (it + 1 < T_LEN && t < (BCH * G3) / 4) {
            const int tn = dir ? (T_LEN - 2 - it) : (it + 1);
            pre = *(const float4*)(xp + ((size_t)tn * B_SZ + l_row) * G3 + l_g);
            pdo = 1;
        }

        // partial hp for rows g0,g1, this thread's k-quarter
        u64 a0[BCH], a1[BCH];
        #pragma unroll
        for (int b = 0; b < BCH; b++) { a0[b] = pack2(bg0, 0.f); a1[b] = pack2(bg1, 0.f); }
        const ulonglong2* h2 = (const ulonglong2*)h_s + q * 6;  // row = 24 u2
        #pragma unroll
        for (int kk = 0; kk < 6; kk++) {
            #pragma unroll
            for (int b = 0; b < BCH; b++) {
                ulonglong2 hv = h2[b * 24 + kk];
                a0[b] = ffma2(hv.x, wa[2 * kk],     a0[b]);
                a0[b] = ffma2(hv.y, wa[2 * kk + 1], a0[b]);
                a1[b] = ffma2(hv.x, wb[2 * kk],     a1[b]);
                a1[b] = ffma2(hv.y, wb[2 * kk + 1], a1[b]);
            }
        }

        // combine quarters + stage pre-activations (store duty split by q=b&3)
        const float* xq_cur = xq_s[buf];
        #pragma unroll
        for (int b = 0; b < BCH; b++) {
            float v0 = qreduce(hsum2(a0[b]));
            float v1 = qreduce(hsum2(a1[b]));
            if ((b & 3) == q) {
                // g0 < 144 < 192: always r/z region
                s_s[b][g0] = v0 + xq_cur[b * G3 + g0];
                if (g1 < 2 * H_SZ) {
                    s_s[b][g1] = v1 + xq_cur[b * G3 + g1];
                } else {
                    s_s[b][g1] = v1;                              // hp_n
                    xn_s[b][g1 - 2 * H_SZ] = xq_cur[b * G3 + g1]; // xp_n
                }
            }
        }
        __syncthreads();

        // gates: BCH*96 = 672 outputs over 576 threads (2nd pass for t < 96)
        #pragma unroll
        for (int oo = 0; oo < 2; oo++) {
            const int o = t + oo * NTHR;
            if (o < BCH * H_SZ) {
                const int b = o / H_SZ;
                const int j = o % H_SZ;
                const float r = fast_sigmoid(s_s[b][j]);
                const float z = fast_sigmoid(s_s[b][H_SZ + j]);
                const float n = fast_tanh(fmaf(r, s_s[b][2 * H_SZ + j], xn_s[b][j]));
                const float hold = h_s[b][j];
                const float hn = fmaf(z, hold - n, n);   // (1-z)*n + z*h
                h_s[b][j] = hn;
                if (b0 + b < B_SZ)
                    out[((size_t)tc * B_SZ + (b0 + b)) * (2 * H_SZ) + dir * H_SZ + j] = hn;
            }
        }
        // stash prefetched xq for next step
        if (pdo) ((float4*)xq_s[buf ^ 1])[t] = pre;
        __syncthreads();
        buf ^= 1;
    }
}

extern "C" void kernel_launch(void* const* d_in, const int* in_sizes, int n_in,
                              void* d_out, int out_size) {
    const float* x    = (const float*)d_in[0];
    const float* wihf = (const float*)d_in[1];
    const float* whhf = (const float*)d_in[2];
    const float* bihf = (const float*)d_in[3];
    const float* bhhf = (const float*)d_in[4];
    const float* wihb = (const float*)d_in[5];
    const float* whhb = (const float*)d_in[6];
    const float* bihb = (const float*)d_in[7];
    const float* bhhb = (const float*)d_in[8];
    float* out = (float*)d_out;

    proj_kernel<<<148, NTHR>>>(x, wihf, bihf, wihb, bihb);
    dim3 sg(NCHUNK, 2);
    scan_kernel<<<sg, NTHR>>>(whhf, bhhf, whhb, bhhb, out);
}

// round 10
// speedup vs baseline: 1.3189x; 1.3189x over previous
#include <cuda_runtime.h>

#define T_LEN 512
#define B_SZ  512
#define I_SZ  100
#define H_SZ  96
#define G3    288   // 3*H
#define BCH   7     // batch rows per scan block (74 chunks x 2 dirs = 148 blocks)
#define NCHUNK 74
#define PROJ_T 576
#define SCAN_T 384   // 96 j x 4 k-quarters
#define HPAD  100    // padded h row (bank-conflict-free duty stores)

typedef unsigned long long u64;

// Scratch: input projections for both directions: [2][T][B][3H] fp32
static __device__ float g_xproj[2ull * T_LEN * B_SZ * G3];

// ---- packed fp32x2 helpers (sm_103a FFMA2 path; bit-identical to 2x fmaf) ----
__device__ __forceinline__ u64 ffma2(u64 a, u64 b, u64 c) {
    u64 d;
    asm("fma.rn.f32x2 %0, %1, %2, %3;" : "=l"(d) : "l"(a), "l"(b), "l"(c));
    return d;
}
__device__ __forceinline__ u64 pack2(float lo, float hi) {
    u64 p;
    asm("mov.b64 %0, {%1, %2};" : "=l"(p) : "f"(lo), "f"(hi));
    return p;
}
__device__ __forceinline__ float hsum2(u64 p) {
    float lo, hi;
    asm("mov.b64 {%0, %1}, %2;" : "=f"(lo), "=f"(hi) : "l"(p));
    return lo + hi;
}
// combine the 4 k-quarter partials held by lanes l, l^8, l^16, l^24
__device__ __forceinline__ float qreduce(float v) {
    v += __shfl_xor_sync(0xffffffffu, v, 8);
    v += __shfl_xor_sync(0xffffffffu, v, 16);
    return v;
}

__device__ __forceinline__ float fast_sigmoid(float x) {
    float e, r;
    asm("ex2.approx.f32 %0, %1;" : "=f"(e) : "f"(-1.4426950408889634f * x));
    asm("rcp.approx.f32 %0, %1;" : "=f"(r) : "f"(1.0f + e));
    return r;
}
__device__ __forceinline__ float fast_tanh(float x) {
    float e, r;
    asm("ex2.approx.f32 %0, %1;" : "=f"(e) : "f"(-2.8853900817779268f * x));
    asm("rcp.approx.f32 %0, %1;" : "=f"(r) : "f"(1.0f + e));
    return 2.0f * r - 1.0f;
}

// ---------------------------------------------------------------------------
// Projection (R6 version): 576 threads, warp w covers g in [16w,16w+16);
// lanes 0-15 = k-half 0, lanes 16-31 = k-half 1; shfl.bfly(16) combine.
// ---------------------------------------------------------------------------
__global__ __launch_bounds__(PROJ_T, 1) void proj_kernel(
    const float* __restrict__ x,
    const float* __restrict__ w_ih_f, const float* __restrict__ b_ih_f,
    const float* __restrict__ w_ih_b, const float* __restrict__ b_ih_b)
{
    const int dir    = blockIdx.x & 1;
    const int chunk  = blockIdx.x >> 1;
    const int nchunk = gridDim.x >> 1;
    const long R = (long)T_LEN * B_SZ;
    const long rows_per = (R + nchunk - 1) / nchunk;
    const long r0 = (long)chunk * rows_per;
    const long r1 = (r0 + rows_per < R) ? (r0 + rows_per) : R;

    const float* w    = dir ? w_ih_b : w_ih_f;
    const float* bias = dir ? b_ih_b : b_ih_f;
    float* xp = g_xproj + (size_t)dir * T_LEN * B_SZ * G3;

    const int t    = threadIdx.x;
    const int lane = t & 31;
    const int g    = (t >> 5) * 16 + (lane & 15);
    const int half = (lane >> 4);

    u64 wr2[26];
    {
        const u64* wrow = (const u64*)(w + g * I_SZ + half * 48);
        #pragma unroll
        for (int k = 0; k < 24; k++) wr2[k] = wrow[k];
        wr2[24] = half ? wrow[24] : 0ull;
        wr2[25] = half ? wrow[25] : 0ull;
    }
    const float bg = half ? 0.0f : bias[g];

    __shared__ __align__(16) float4 xs4[2][16 * 25];

    {
        int nr = (int)((r1 - r0 < 16) ? (r1 - r0) : 16);
        const float4* src = (const float4*)(x + r0 * I_SZ);
        if (t < nr * 25) xs4[0][t] = src[t];
    }
    __syncthreads();

    int buf = 0;
    for (long row0 = r0; row0 < r1; row0 += 16, buf ^= 1) {
        const int nr = (int)((r1 - row0 < 16) ? (r1 - row0) : 16);

        float4 pre0;
        int pdo = 0;
        const long nrow0 = row0 + 16;
        if (nrow0 < r1) {
            const int nnr = (int)((r1 - nrow0 < 16) ? (r1 - nrow0) : 16);
            const float4* nsrc = (const float4*)(x + nrow0 * I_SZ);
            if (t < nnr * 25) { pre0 = nsrc[t]; pdo = 1; }
        }

        const ulonglong2* xb2 = (const ulonglong2*)xs4[buf] + half * 12;
        for (int sub = 0; sub < nr; sub += 4) {
            u64 a0 = pack2(bg, 0.0f);
            u64 a1 = pack2(bg, 0.0f);
            u64 a2 = pack2(bg, 0.0f);
            u64 a3 = pack2(bg, 0.0f);
            #pragma unroll
            for (int kk = 0; kk < 13; kk++) {
                ulonglong2 va = xb2[(sub + 0) * 25 + kk];
                ulonglong2 vb = xb2[(sub + 1) * 25 + kk];
                ulonglong2 vc = xb2[(sub + 2) * 25 + kk];
                ulonglong2 vd = xb2[(sub + 3) * 25 + kk];
                a0 = ffma2(va.x, wr2[2 * kk],     a0);
                a0 = ffma2(va.y, wr2[2 * kk + 1], a0);
                a1 = ffma2(vb.x, wr2[2 * kk],     a1);
                a1 = ffma2(vb.y, wr2[2 * kk + 1], a1);
                a2 = ffma2(vc.x, wr2[2 * kk],     a2);
                a2 = ffma2(vc.y, wr2[2 * kk + 1], a2);
                a3 = ffma2(vd.x, wr2[2 * kk],     a3);
                a3 = ffma2(vd.y, wr2[2 * kk + 1], a3);
            }
            float s0 = hsum2(a0); s0 += __shfl_xor_sync(0xffffffffu, s0, 16);
            float s1 = hsum2(a1); s1 += __shfl_xor_sync(0xffffffffu, s1, 16);
            float s2 = hsum2(a2); s2 += __shfl_xor_sync(0xffffffffu, s2, 16);
            float s3 = hsum2(a3); s3 += __shfl_xor_sync(0xffffffffu, s3, 16);
            if (half == 0) {
                if (row0 + sub + 0 < r1) xp[(row0 + sub + 0) * G3 + g] = s0;
                if (row0 + sub + 1 < r1) xp[(row0 + sub + 1) * G3 + g] = s1;
            } else {
                if (row0 + sub + 2 < r1) xp[(row0 + sub + 2) * G3 + g] = s2;
                if (row0 + sub + 3 < r1) xp[(row0 + sub + 3) * G3 + g] = s3;
            }
        }

        if (pdo) xs4[buf ^ 1][t] = pre0;
        __syncthreads();
    }
}

// ---------------------------------------------------------------------------
// Scan: 384 threads. Thread = (j, q): j = warp*8 + (lane&7) in [0,96),
// q = lane>>3 = k-quarter. Owns gate rows j, j+96, j+192.
// After quartet shfl-reduce, the duty lane (batches q and q+4) computes the
// full gate in registers and writes new h. h double-buffered in smem
// (rows padded to 100 floats) -> ONE __syncthreads per step.
// ---------------------------------------------------------------------------
__global__ __launch_bounds__(SCAN_T, 1) void scan_kernel(
    const float* __restrict__ w_hh_f, const float* __restrict__ b_hh_f,
    const float* __restrict__ w_hh_b, const float* __restrict__ b_hh_b,
    float* __restrict__ out)
{
    const int dir = blockIdx.y;
    const int b0  = blockIdx.x * BCH;
    const float* w    = dir ? w_hh_b : w_hh_f;
    const float* bias = dir ? b_hh_b : b_hh_f;
    const float* xp = g_xproj + (size_t)dir * T_LEN * B_SZ * G3;

    const int t    = threadIdx.x;
    const int lane = t & 31;
    const int q    = lane >> 3;
    const int j    = (t >> 5) * 8 + (lane & 7);   // 0..95

    // weights: rows j, j+96, j+192; k in [24q, 24q+24): 12 u64 each
    u64 wr[3][12];
    #pragma unroll
    for (int r = 0; r < 3; r++) {
        const u64* p = (const u64*)(w + (j + 96 * r) * H_SZ + 24 * q);
        #pragma unroll
        for (int k = 0; k < 12; k++) wr[r][k] = p[k];
    }
    float bg[3];
    #pragma unroll
    for (int r = 0; r < 3; r++) bg[r] = q ? 0.0f : bias[j + 96 * r];

    // double-buffered hidden state, rows padded to HPAD floats
    __shared__ __align__(16) float h_s[2][BCH][HPAD];
    for (int idx = t; idx < 2 * BCH * HPAD; idx += SCAN_T) ((float*)h_s)[idx] = 0.0f;

    // duty batches for this lane: b = q and q+4
    const int bd0 = q;
    const int bd1 = q + 4;               // valid iff < BCH
    const bool d1v = (bd1 < BCH);
    int row0 = b0 + bd0; if (row0 > B_SZ - 1) row0 = B_SZ - 1;
    int row1 = b0 + (d1v ? bd1 : 0); if (row1 > B_SZ - 1) row1 = B_SZ - 1;
    const bool w0v = (b0 + bd0 < B_SZ);
    const bool w1v = d1v && (b0 + bd1 < B_SZ);

    float hold0 = 0.0f, hold1 = 0.0f;    // this lane's h[b][j], prev step

    // prime xq for step 0 (duty lanes)
    float xq0[3], xq1[3];
    {
        const int t0 = dir ? (T_LEN - 1) : 0;
        const float* p0 = xp + ((size_t)t0 * B_SZ + row0) * G3 + j;
        const float* p1 = xp + ((size_t)t0 * B_SZ + row1) * G3 + j;
        #pragma unroll
        for (int r = 0; r < 3; r++) {
            xq0[r] = p0[96 * r];
            xq1[r] = d1v ? p1[96 * r] : 0.0f;
        }
    }
    __syncthreads();

    int p = 0;
    for (int it = 0; it < T_LEN; it++) {
        const int tc = dir ? (T_LEN - 1 - it) : it;

        // prefetch next step's xq (DRAM latency hidden under this step)
        float xn0[3], xn1[3];
        #pragma unroll
        for (int r = 0; r < 3; r++) { xn0[r] = 0.0f; xn1[r] = 0.0f; }
        if (it + 1 < T_LEN) {
            const int tn = dir ? (T_LEN - 2 - it) : (it + 1);
            const float* p0 = xp + ((size_t)tn * B_SZ + row0) * G3 + j;
            const float* p1 = xp + ((size_t)tn * B_SZ + row1) * G3 + j;
            #pragma unroll
            for (int r = 0; r < 3; r++) {
                xn0[r] = p0[96 * r];
                xn1[r] = d1v ? p1[96 * r] : 0.0f;
            }
        }

        // partial hp for 3 rows x BCH batches, this thread's k-quarter
        u64 acc[3][BCH];
        #pragma unroll
        for (int r = 0; r < 3; r++)
            #pragma unroll
            for (int b = 0; b < BCH; b++) acc[r][b] = pack2(bg[r], 0.0f);

        const ulonglong2* h2 = (const ulonglong2*)h_s[p] + q * 6;  // row = 25 u2
        #pragma unroll
        for (int kk = 0; kk < 6; kk++) {
            #pragma unroll
            for (int b = 0; b < BCH; b++) {
                ulonglong2 hv = h2[b * (HPAD / 4) + kk];
                #pragma unroll
                for (int r = 0; r < 3; r++) {
                    acc[r][b] = ffma2(hv.x, wr[r][2 * kk],     acc[r][b]);
                    acc[r][b] = ffma2(hv.y, wr[r][2 * kk + 1], acc[r][b]);
                }
            }
        }

        // reduce quartets; keep only this lane's duty batches (less reg pressure)
        float v0d[3], v1d[3];
        #pragma unroll
        for (int r = 0; r < 3; r++) {
            #pragma unroll
            for (int b = 0; b < BCH; b++) {
                const float vv = qreduce(hsum2(acc[r][b]));
                if (b == bd0) v0d[r] = vv;
                if (d1v && b == bd1) v1d[r] = vv;
            }
        }

        // duty lane computes gates fully in registers, writes new h
        {
            const float rg = fast_sigmoid(v0d[0] + xq0[0]);
            const float zg = fast_sigmoid(v0d[1] + xq0[1]);
            const float ng = fast_tanh(fmaf(rg, v0d[2], xq0[2]));
            const float hn = fmaf(zg, hold0 - ng, ng);
            hold0 = hn;
            h_s[p ^ 1][bd0][j] = hn;
            if (w0v)
                out[((size_t)tc * B_SZ + (b0 + bd0)) * (2 * H_SZ) + dir * H_SZ + j] = hn;
        }
        if (d1v) {
            const float rg = fast_sigmoid(v1d[0] + xq1[0]);
            const float zg = fast_sigmoid(v1d[1] + xq1[1]);
            const float ng = fast_tanh(fmaf(rg, v1d[2], xq1[2]));
            const float hn = fmaf(zg, hold1 - ng, ng);
            hold1 = hn;
            h_s[p ^ 1][bd1][j] = hn;
            if (w1v)
                out[((size_t)tc * B_SZ + (b0 + bd1)) * (2 * H_SZ) + dir * H_SZ + j] = hn;
        }

        #pragma unroll
        for (int r = 0; r < 3; r++) { xq0[r] = xn0[r]; xq1[r] = xn1[r]; }

        __syncthreads();
        p ^= 1;
    }
}

extern "C" void kernel_launch(void* const* d_in, const int* in_sizes, int n_in,
                              void* d_out, int out_size) {
    const float* x    = (const float*)d_in[0];
    const float* wihf = (const float*)d_in[1];
    const float* whhf = (const float*)d_in[2];
    const float* bihf = (const float*)d_in[3];
    const float* bhhf = (const float*)d_in[4];
    const float* wihb = (const float*)d_in[5];
    const float* whhb = (const float*)d_in[6];
    const float* bihb = (const float*)d_in[7];
    const float* bhhb = (const float*)d_in[8];
    float* out = (float*)d_out;

    proj_kernel<<<148, PROJ_T>>>(x, wihf, bihf, wihb, bihb);
    dim3 sg(NCHUNK, 2);
    scan_kernel<<<sg, SCAN_T>>>(whhf, bhhf, whhb, bhhb, out);
}